// round 2
// baseline (speedup 1.0000x reference)
#include <cuda_runtime.h>
#include <math.h>

#define H       128
#define NNODES  50000
#define NEDGES  600000
#define NTYPES  9          // NUM_EDGE_TYPES + 1 rows in edge_embed
#define TM      64
#define TN      128
#define GEMM_THREADS 256
#define GEMM_SMEM ((TM*H + H*(TN+1)) * sizeof(float))   // As + Bs(pitch 129)

// fused GRU GEMM config
#define FTM     64          // rows per block
#define FTHREADS 512
#define KC      64          // K chunk
#define BPITCH  385         // Bs pitch (384 cols + 1, conflict-free STS/LDS)
#define FUSED_SMEM ((2*FTM*KC + KC*BPITCH) * sizeof(float))  // 131328 B

// scan config
#define SBLK    512
#define NSB     ((NNODES + SBLK - 1) / SBLK)   // 98

// ---------------- scratch (static device globals; no runtime alloc) ----------
__device__ float g_hW [NNODES * H];        // h @ W_msg^T + b_msg
__device__ float g_msg[NNODES * H];        // segment-summed messages
__device__ int   g_deg [NNODES];
__device__ int   g_off [NNODES + 1];
__device__ int   g_cur [NNODES];
__device__ int   g_perm[NEDGES];
__device__ int   g_bsum[NSB];
__device__ int   g_bpre[NSB];

// ---------------- tiny helpers ----------------
__global__ void zero_deg_kernel() {
    int i = blockIdx.x * blockDim.x + threadIdx.x;
    if (i < NNODES) g_deg[i] = 0;
}

__global__ void count_kernel(const int* __restrict__ edge_index) {
    int e = blockIdx.x * blockDim.x + threadIdx.x;
    if (e < NEDGES) {
        int d = edge_index[NEDGES + e];   // dst row
        atomicAdd(&g_deg[d], 1);
    }
}

// ---- scan stage 1: per-block sums over SBLK-element tiles ----
__global__ void scan1_kernel() {
    int tid = threadIdx.x;
    int i = blockIdx.x * SBLK + tid;
    int v = (i < NNODES) ? g_deg[i] : 0;
    #pragma unroll
    for (int o = 16; o > 0; o >>= 1) v += __shfl_down_sync(0xffffffffu, v, o);
    __shared__ int ws[SBLK / 32];
    if ((tid & 31) == 0) ws[tid >> 5] = v;
    __syncthreads();
    if (tid < 32) {
        int s = (tid < SBLK / 32) ? ws[tid] : 0;
        #pragma unroll
        for (int o = 16; o > 0; o >>= 1) s += __shfl_down_sync(0xffffffffu, s, o);
        if (tid == 0) g_bsum[blockIdx.x] = s;
    }
}

// ---- scan stage 2: single small block scans the 98 block sums ----
__global__ void scan2_kernel() {
    __shared__ int s[128];
    int tid = threadIdx.x;
    int v = (tid < NSB) ? g_bsum[tid] : 0;
    s[tid] = v;
    __syncthreads();
    #pragma unroll
    for (int o = 1; o < 128; o <<= 1) {
        int y = (tid >= o) ? s[tid - o] : 0;
        __syncthreads();
        s[tid] += y;
        __syncthreads();
    }
    if (tid < NSB) g_bpre[tid] = s[tid] - v;   // exclusive
    if (tid == 127) g_off[NNODES] = s[127];
}

// ---- scan stage 3: block-local exclusive scan + block prefix -> off/cur ----
__global__ void scan3_kernel() {
    int tid = threadIdx.x;
    int i = blockIdx.x * SBLK + tid;
    int v = (i < NNODES) ? g_deg[i] : 0;
    int lane = tid & 31, wid = tid >> 5;
    int x = v;
    #pragma unroll
    for (int o = 1; o < 32; o <<= 1) {
        int y = __shfl_up_sync(0xffffffffu, x, o);
        if (lane >= o) x += y;
    }
    __shared__ int wsum[SBLK / 32];
    if (lane == 31) wsum[wid] = x;
    __syncthreads();
    if (wid == 0) {
        int w = (lane < SBLK / 32) ? wsum[lane] : 0;
        #pragma unroll
        for (int o = 1; o < SBLK / 32; o <<= 1) {
            int y = __shfl_up_sync(0xffffffffu, w, o);
            if (lane >= o) w += y;
        }
        if (lane < SBLK / 32) wsum[lane] = w;
    }
    __syncthreads();
    int excl = x - v + (wid > 0 ? wsum[wid - 1] : 0) + g_bpre[blockIdx.x];
    if (i < NNODES) { g_off[i] = excl; g_cur[i] = excl; }
}

__global__ void scatter_kernel(const int* __restrict__ edge_index) {
    int e = blockIdx.x * blockDim.x + threadIdx.x;
    if (e < NEDGES) {
        int d = edge_index[NEDGES + e];
        int pos = atomicAdd(&g_cur[d], 1);
        g_perm[pos] = e;
    }
}

// ---------------- GEMM: C[M,N] = A[M,128] @ B[N,128]^T + bias[N] -------------
// (used only for hW = h @ W_msg^T + b_msg)
__global__ __launch_bounds__(GEMM_THREADS)
void gemm_bias(const float* __restrict__ A, const float* __restrict__ B,
               const float* __restrict__ bias, float* __restrict__ C,
               int M, int N) {
    extern __shared__ float sm[];
    float* As = sm;                // [TM][128]
    float* Bs = sm + TM * H;       // [128][TN+1]

    const int m0  = blockIdx.x * TM;
    const int n0  = blockIdx.y * TN;
    const int tid = threadIdx.x;

    for (int i = tid; i < TM * (H / 4); i += GEMM_THREADS) {
        int r  = i >> 5;
        int c4 = i & 31;
        int gm = m0 + r;
        float4 v = make_float4(0.f, 0.f, 0.f, 0.f);
        if (gm < M) v = *(const float4*)(A + (size_t)gm * H + c4 * 4);
        *(float4*)(As + r * H + c4 * 4) = v;
    }
    for (int i = tid; i < TN * H; i += GEMM_THREADS) {
        int n = i >> 7;
        int k = i & 127;
        Bs[k * (TN + 1) + n] = B[(size_t)(n0 + n) * H + k];
    }
    __syncthreads();

    const int lane = tid & 31;
    const int mg   = tid >> 5;

    float acc[8][4];
    #pragma unroll
    for (int q = 0; q < 4; q++) {
        float b = bias[n0 + lane + 32 * q];
        #pragma unroll
        for (int i = 0; i < 8; i++) acc[i][q] = b;
    }

    #pragma unroll 4
    for (int k = 0; k < H; k++) {
        float b0 = Bs[k * (TN + 1) + lane];
        float b1 = Bs[k * (TN + 1) + lane + 32];
        float b2 = Bs[k * (TN + 1) + lane + 64];
        float b3 = Bs[k * (TN + 1) + lane + 96];
        #pragma unroll
        for (int i = 0; i < 8; i++) {
            float a = As[(mg * 8 + i) * H + k];
            acc[i][0] = fmaf(a, b0, acc[i][0]);
            acc[i][1] = fmaf(a, b1, acc[i][1]);
            acc[i][2] = fmaf(a, b2, acc[i][2]);
            acc[i][3] = fmaf(a, b3, acc[i][3]);
        }
    }

    #pragma unroll
    for (int i = 0; i < 8; i++) {
        int gm = m0 + mg * 8 + i;
        if (gm < M) {
            #pragma unroll
            for (int q = 0; q < 4; q++)
                C[(size_t)gm * N + n0 + lane + 32 * q] = acc[i][q];
        }
    }
}

// ---------------- aggregate: warp per node, float4 per lane ------------------
__global__ void aggregate_kernel(const int* __restrict__ edge_index,
                                 const int* __restrict__ etype,
                                 const float* __restrict__ emb) {
    int warp = (blockIdx.x * blockDim.x + threadIdx.x) >> 5;
    int lane = threadIdx.x & 31;
    if (warp >= NNODES) return;
    int s0 = g_off[warp];
    int s1 = g_off[warp + 1];
    float4 acc = make_float4(0.f, 0.f, 0.f, 0.f);
    for (int i = s0; i < s1; i++) {
        int e = g_perm[i];
        int s = edge_index[e];
        int t = etype[e];
        t = min(max(t, 0), NTYPES - 1);
        float4 hv = *((const float4*)(g_hW + (size_t)s * H) + lane);
        float4 ev = *((const float4*)(emb  + (size_t)t * H) + lane);
        acc.x += hv.x + ev.x;
        acc.y += hv.y + ev.y;
        acc.z += hv.z + ev.z;
        acc.w += hv.w + ev.w;
    }
    *((float4*)(g_msg + (size_t)warp * H) + lane) = acc;
}

// ---------------- fused: gi = msg@W_ih^T+b_ih, gh = h@W_hh^T+b_hh, GRU gates --
// Block computes 64 rows x 32 output columns. For output column j it needs
// gi/gh at columns {j, j+128, j+256}: 6 accumulator sets per thread-row.
// Bs columns: [0,96)=W_ih gates r/z/n, [192,288)... actually [0,192)=ih, [192,384)=hh.
__global__ __launch_bounds__(FTHREADS)
void fused_gru_kernel(const float* __restrict__ Amsg, const float* __restrict__ h,
                      const float* __restrict__ W_ih, const float* __restrict__ W_hh,
                      const float* __restrict__ b_ih, const float* __restrict__ b_hh,
                      float* __restrict__ out) {
    extern __shared__ float sm[];
    float* As1 = sm;                    // [64][KC]  msg
    float* As2 = sm + FTM * KC;         // [64][KC]  h
    float* Bs  = sm + 2 * FTM * KC;     // [KC][BPITCH]  (384 cols used)

    const int tid  = threadIdx.x;
    const int lane = tid & 31;
    const int grp  = tid >> 5;          // 0..15, 4 rows each
    const int m0   = blockIdx.x * FTM;
    const int c0   = blockIdx.y * 32;   // output column chunk

    float acc[4][6];
    #pragma unroll
    for (int r = 0; r < 4; r++)
        #pragma unroll
        for (int q = 0; q < 6; q++) acc[r][q] = 0.f;

    #pragma unroll
    for (int kc = 0; kc < H / KC; kc++) {
        // load A tiles (float4, coalesced); 1024 float4 per tile, 2 per thread
        #pragma unroll
        for (int l = 0; l < 2; l++) {
            int i  = tid + l * FTHREADS;
            int r  = i >> 4;            // /16
            int c4 = i & 15;
            int gm = m0 + r;
            float4 v1 = make_float4(0.f,0.f,0.f,0.f), v2 = v1;
            if (gm < NNODES) {
                v1 = *(const float4*)(Amsg + (size_t)gm * H + kc * KC + c4 * 4);
                v2 = *(const float4*)(h    + (size_t)gm * H + kc * KC + c4 * 4);
            }
            *(float4*)(As1 + r * KC + c4 * 4) = v1;
            *(float4*)(As2 + r * KC + c4 * 4) = v2;
        }
        // load Bs: col c in [0,384): c<192 -> W_ih, else W_hh; g=(c%192)>>5, j=c&31
        // Bs[k][c] = W[(g*128 + c0 + j)*128 + kc*64 + k]; consecutive tid -> consec k (coalesced)
        for (int i = tid; i < 384 * KC; i += FTHREADS) {
            int c = i >> 6;             // /64
            int k = i & 63;
            int cc = c < 192 ? c : c - 192;
            int g = cc >> 5;
            int j = cc & 31;
            const float* W = (c < 192) ? W_ih : W_hh;
            Bs[k * BPITCH + c] = W[(size_t)(g * 128 + c0 + j) * H + kc * KC + k];
        }
        __syncthreads();

        #pragma unroll 4
        for (int k = 0; k < KC; k++) {
            float bi0 = Bs[k * BPITCH + lane];
            float bi1 = Bs[k * BPITCH + 32 + lane];
            float bi2 = Bs[k * BPITCH + 64 + lane];
            float bh0 = Bs[k * BPITCH + 192 + lane];
            float bh1 = Bs[k * BPITCH + 224 + lane];
            float bh2 = Bs[k * BPITCH + 256 + lane];
            #pragma unroll
            for (int r = 0; r < 4; r++) {
                float a1 = As1[(grp * 4 + r) * KC + k];
                float a2 = As2[(grp * 4 + r) * KC + k];
                acc[r][0] = fmaf(a1, bi0, acc[r][0]);
                acc[r][1] = fmaf(a1, bi1, acc[r][1]);
                acc[r][2] = fmaf(a1, bi2, acc[r][2]);
                acc[r][3] = fmaf(a2, bh0, acc[r][3]);
                acc[r][4] = fmaf(a2, bh1, acc[r][4]);
                acc[r][5] = fmaf(a2, bh2, acc[r][5]);
            }
        }
        __syncthreads();
    }

    // epilogue: add biases, gate math, write out
    float bir = b_ih[c0 + lane];
    float biz = b_ih[128 + c0 + lane];
    float bin = b_ih[256 + c0 + lane];
    float bhr = b_hh[c0 + lane];
    float bhz = b_hh[128 + c0 + lane];
    float bhn = b_hh[256 + c0 + lane];

    #pragma unroll
    for (int r = 0; r < 4; r++) {
        int gm = m0 + grp * 4 + r;
        if (gm < NNODES) {
            float ir = acc[r][0] + bir, iz = acc[r][1] + biz, in_ = acc[r][2] + bin;
            float hr = acc[r][3] + bhr, hz = acc[r][4] + bhz, hn  = acc[r][5] + bhn;
            float rr = 1.f / (1.f + __expf(-(ir + hr)));
            float zz = 1.f / (1.f + __expf(-(iz + hz)));
            float nn = tanhf(in_ + rr * hn);
            float hv = h[(size_t)gm * H + c0 + lane];
            out[(size_t)gm * H + c0 + lane] = (1.f - zz) * nn + zz * hv;
        }
    }
}

// ---------------- launch ------------------------------------------------------
extern "C" void kernel_launch(void* const* d_in, const int* in_sizes, int n_in,
                              void* d_out, int out_size) {
    const float* h     = (const float*)d_in[0];
    const int*   eidx  = (const int*)  d_in[1];   // [2, E]
    const int*   etype = (const int*)  d_in[2];
    const float* W_msg = (const float*)d_in[4];
    const float* b_msg = (const float*)d_in[5];
    const float* emb   = (const float*)d_in[6];
    const float* W_ih  = (const float*)d_in[7];
    const float* W_hh  = (const float*)d_in[8];
    const float* b_ih  = (const float*)d_in[9];
    const float* b_hh  = (const float*)d_in[10];
    float* out = (float*)d_out;

    float *hW, *msg;
    cudaGetSymbolAddress((void**)&hW,  g_hW);
    cudaGetSymbolAddress((void**)&msg, g_msg);

    cudaFuncSetAttribute(gemm_bias, cudaFuncAttributeMaxDynamicSharedMemorySize,
                         (int)GEMM_SMEM);
    cudaFuncSetAttribute(fused_gru_kernel, cudaFuncAttributeMaxDynamicSharedMemorySize,
                         (int)FUSED_SMEM);

    const int MTILES = (NNODES + TM - 1) / TM;     // 782
    const int FTILES = (NNODES + FTM - 1) / FTM;   // 782

    zero_deg_kernel<<<(NNODES + 255) / 256, 256>>>();
    count_kernel  <<<(NEDGES + 255) / 256, 256>>>(eidx);
    gemm_bias<<<dim3(MTILES, 1), GEMM_THREADS, GEMM_SMEM>>>(h, W_msg, b_msg, hW,
                                                            NNODES, H);
    scan1_kernel<<<NSB, SBLK>>>();
    scan2_kernel<<<1, 128>>>();
    scan3_kernel<<<NSB, SBLK>>>();
    scatter_kernel<<<(NEDGES + 255) / 256, 256>>>(eidx);
    aggregate_kernel<<<(NNODES * 32 + 255) / 256, 256>>>(eidx, etype, emb);
    fused_gru_kernel<<<dim3(FTILES, 4), FTHREADS, FUSED_SMEM>>>(
        msg, h, W_ih, W_hh, b_ih, b_hh, out);
}

// round 4
// speedup vs baseline: 2.3124x; 2.3124x over previous
#include <cuda_runtime.h>
#include <cuda_bf16.h>
#include <math.h>
#include <stdint.h>

#define H       128
#define NNODES  50000
#define NEDGES  600000
#define NTYPES  9

// scan config
#define SBLK    512
#define NSB     ((NNODES + SBLK - 1) / SBLK)   // 98

// mma gemm config
#define PITCH   136                 // bf16 units; 272B rows -> ldmatrix conflict-free
#define MMA_SMEM ((2*128*PITCH + 2*64*PITCH) * 2)   // 104448 B

// ---------------- scratch ----------------
__device__ float g_hW [NNODES * H];
__device__ float g_gi [NNODES * 3 * H];
__device__ float g_gh [NNODES * 3 * H];
__device__ __nv_bfloat16 g_hhi[NNODES * H];
__device__ __nv_bfloat16 g_hlo[NNODES * H];
__device__ __nv_bfloat16 g_mhi[NNODES * H];
__device__ __nv_bfloat16 g_mlo[NNODES * H];
__device__ __nv_bfloat16 g_whi[(128 + 384 + 384) * H];   // W_msg | W_ih | W_hh
__device__ __nv_bfloat16 g_wlo[(128 + 384 + 384) * H];
__device__ int   g_deg [NNODES];
__device__ int   g_off [NNODES + 1];
__device__ int   g_cur [NNODES];
__device__ int   g_perm[NEDGES];
__device__ int   g_bsum[NSB];
__device__ int   g_bpre[NSB];

// ---------------- helpers ----------------
__device__ __forceinline__ uint32_t smem_u32(const void* p) {
    uint32_t a;
    asm("{ .reg .u64 t; cvta.to.shared.u64 t, %1; cvt.u32.u64 %0, t; }"
        : "=r"(a) : "l"(p));
    return a;
}

#define LDSM4(R, addr) \
    asm volatile("ldmatrix.sync.aligned.m8n8.x4.shared.b16 {%0,%1,%2,%3}, [%4];" \
        : "=r"((R)[0]), "=r"((R)[1]), "=r"((R)[2]), "=r"((R)[3]) : "r"(addr))

#define MMA_BF16(D, A, B0, B1) \
    asm volatile("mma.sync.aligned.m16n8k16.row.col.f32.bf16.bf16.f32 " \
        "{%0,%1,%2,%3}, {%4,%5,%6,%7}, {%8,%9}, {%0,%1,%2,%3};" \
        : "+f"((D)[0]), "+f"((D)[1]), "+f"((D)[2]), "+f"((D)[3]) \
        : "r"((A)[0]), "r"((A)[1]), "r"((A)[2]), "r"((A)[3]), "r"(B0), "r"(B1))

__device__ __forceinline__ uint32_t pack_bf2(__nv_bfloat16 a, __nv_bfloat16 b) {
    __nv_bfloat162 v; v.x = a; v.y = b;
    return *(uint32_t*)&v;
}

// ---------------- graph prep ----------------
__global__ void zero_deg_kernel() {
    int i = blockIdx.x * blockDim.x + threadIdx.x;
    if (i < NNODES) g_deg[i] = 0;
}
__global__ void count_kernel(const int* __restrict__ edge_index) {
    int e = blockIdx.x * blockDim.x + threadIdx.x;
    if (e < NEDGES) atomicAdd(&g_deg[edge_index[NEDGES + e]], 1);
}
__global__ void scan1_kernel() {
    int tid = threadIdx.x;
    int i = blockIdx.x * SBLK + tid;
    int v = (i < NNODES) ? g_deg[i] : 0;
    #pragma unroll
    for (int o = 16; o > 0; o >>= 1) v += __shfl_down_sync(0xffffffffu, v, o);
    __shared__ int ws[SBLK / 32];
    if ((tid & 31) == 0) ws[tid >> 5] = v;
    __syncthreads();
    if (tid < 32) {
        int s = (tid < SBLK / 32) ? ws[tid] : 0;
        #pragma unroll
        for (int o = 16; o > 0; o >>= 1) s += __shfl_down_sync(0xffffffffu, s, o);
        if (tid == 0) g_bsum[blockIdx.x] = s;
    }
}
__global__ void scan2_kernel() {
    __shared__ int s[128];
    int tid = threadIdx.x;
    int v = (tid < NSB) ? g_bsum[tid] : 0;
    s[tid] = v;
    __syncthreads();
    #pragma unroll
    for (int o = 1; o < 128; o <<= 1) {
        int y = (tid >= o) ? s[tid - o] : 0;
        __syncthreads();
        s[tid] += y;
        __syncthreads();
    }
    if (tid < NSB) g_bpre[tid] = s[tid] - v;
    if (tid == 127) g_off[NNODES] = s[127];
}
__global__ void scan3_kernel() {
    int tid = threadIdx.x;
    int i = blockIdx.x * SBLK + tid;
    int v = (i < NNODES) ? g_deg[i] : 0;
    int lane = tid & 31, wid = tid >> 5;
    int x = v;
    #pragma unroll
    for (int o = 1; o < 32; o <<= 1) {
        int y = __shfl_up_sync(0xffffffffu, x, o);
        if (lane >= o) x += y;
    }
    __shared__ int wsum[SBLK / 32];
    if (lane == 31) wsum[wid] = x;
    __syncthreads();
    if (wid == 0) {
        int w = (lane < SBLK / 32) ? wsum[lane] : 0;
        #pragma unroll
        for (int o = 1; o < SBLK / 32; o <<= 1) {
            int y = __shfl_up_sync(0xffffffffu, w, o);
            if (lane >= o) w += y;
        }
        if (lane < SBLK / 32) wsum[lane] = w;
    }
    __syncthreads();
    int excl = x - v + (wid > 0 ? wsum[wid - 1] : 0) + g_bpre[blockIdx.x];
    if (i < NNODES) { g_off[i] = excl; g_cur[i] = excl; }
}
__global__ void scatter_kernel(const int* __restrict__ edge_index) {
    int e = blockIdx.x * blockDim.x + threadIdx.x;
    if (e < NEDGES) {
        int pos = atomicAdd(&g_cur[edge_index[NEDGES + e]], 1);
        g_perm[pos] = e;
    }
}

// ---------------- fp32 -> bf16 hi/lo split ----------------
__global__ void convert_kernel(const float* __restrict__ X,
                               __nv_bfloat16* __restrict__ hi,
                               __nv_bfloat16* __restrict__ lo, int n4) {
    int i = blockIdx.x * blockDim.x + threadIdx.x;
    if (i >= n4) return;
    float4 v = ((const float4*)X)[i];
    __nv_bfloat16 hx = __float2bfloat16(v.x), hy = __float2bfloat16(v.y);
    __nv_bfloat16 hz = __float2bfloat16(v.z), hw = __float2bfloat16(v.w);
    uint2 hp, lp;
    hp.x = pack_bf2(hx, hy);
    hp.y = pack_bf2(hz, hw);
    lp.x = pack_bf2(__float2bfloat16(v.x - __bfloat162float(hx)),
                    __float2bfloat16(v.y - __bfloat162float(hy)));
    lp.y = pack_bf2(__float2bfloat16(v.z - __bfloat162float(hz)),
                    __float2bfloat16(v.w - __bfloat162float(hw)));
    ((uint2*)hi)[i] = hp;
    ((uint2*)lo)[i] = lp;
}

// ---------------- aggregate: warp per node, writes bf16 hi/lo msg ------------
__global__ void aggregate_kernel(const int* __restrict__ edge_index,
                                 const int* __restrict__ etype,
                                 const float* __restrict__ emb) {
    int warp = (blockIdx.x * blockDim.x + threadIdx.x) >> 5;
    int lane = threadIdx.x & 31;
    if (warp >= NNODES) return;
    int s0 = g_off[warp];
    int s1 = g_off[warp + 1];
    float4 acc = make_float4(0.f, 0.f, 0.f, 0.f);
    for (int i = s0; i < s1; i++) {
        int e = g_perm[i];
        int s = edge_index[e];
        int t = etype[e];
        t = min(max(t, 0), NTYPES - 1);
        float4 hv = *((const float4*)(g_hW + (size_t)s * H) + lane);
        float4 ev = *((const float4*)(emb  + (size_t)t * H) + lane);
        acc.x += hv.x + ev.x;  acc.y += hv.y + ev.y;
        acc.z += hv.z + ev.z;  acc.w += hv.w + ev.w;
    }
    __nv_bfloat16 hx = __float2bfloat16(acc.x), hy = __float2bfloat16(acc.y);
    __nv_bfloat16 hz = __float2bfloat16(acc.z), hw = __float2bfloat16(acc.w);
    uint2 hp, lp;
    hp.x = pack_bf2(hx, hy);
    hp.y = pack_bf2(hz, hw);
    lp.x = pack_bf2(__float2bfloat16(acc.x - __bfloat162float(hx)),
                    __float2bfloat16(acc.y - __bfloat162float(hy)));
    lp.y = pack_bf2(__float2bfloat16(acc.z - __bfloat162float(hz)),
                    __float2bfloat16(acc.w - __bfloat162float(hw)));
    ((uint2*)(g_mhi + (size_t)warp * H))[lane] = hp;
    ((uint2*)(g_mlo + (size_t)warp * H))[lane] = lp;
}

// ---------------- bf16 2-split tensor GEMM (mma.sync path) -------------------
// C[M,N] = A[M,128] @ W[N,128]^T + bias;  A,W given as bf16 hi/lo planes.
// block: 128(m) x 64(n), 8 warps (4m x 2n), warp tile 32x32, full K in smem.
__global__ __launch_bounds__(256)
void mma_gemm(const __nv_bfloat16* __restrict__ Ahi, const __nv_bfloat16* __restrict__ Alo,
              const __nv_bfloat16* __restrict__ Bhi, const __nv_bfloat16* __restrict__ Blo,
              const float* __restrict__ bias, float* __restrict__ C,
              int M, int N) {
    extern __shared__ __nv_bfloat16 sm[];
    __nv_bfloat16* sAhi = sm;                       // [128][PITCH]
    __nv_bfloat16* sAlo = sm + 128 * PITCH;
    __nv_bfloat16* sBhi = sm + 2 * 128 * PITCH;     // [64][PITCH]
    __nv_bfloat16* sBlo = sm + 2 * 128 * PITCH + 64 * PITCH;

    const int tid = threadIdx.x;
    const int m0 = blockIdx.x * 128;
    const int n0 = blockIdx.y * 64;

    // load A tile (hi+lo), 16B chunks
    for (int i = tid; i < 128 * 16; i += 256) {
        int r = i >> 4, c = i & 15;
        int gr = m0 + r;
        uint4 vh = make_uint4(0, 0, 0, 0), vl = vh;
        if (gr < M) {
            vh = *(const uint4*)(Ahi + (size_t)gr * H + c * 8);
            vl = *(const uint4*)(Alo + (size_t)gr * H + c * 8);
        }
        *(uint4*)(sAhi + r * PITCH + c * 8) = vh;
        *(uint4*)(sAlo + r * PITCH + c * 8) = vl;
    }
    // load B tile (rows n0..n0+63 always valid by grid)
    for (int i = tid; i < 64 * 16; i += 256) {
        int r = i >> 4, c = i & 15;
        int gr = n0 + r;
        *(uint4*)(sBhi + r * PITCH + c * 8) = *(const uint4*)(Bhi + (size_t)gr * H + c * 8);
        *(uint4*)(sBlo + r * PITCH + c * 8) = *(const uint4*)(Blo + (size_t)gr * H + c * 8);
    }
    __syncthreads();

    const int lane = tid & 31;
    const int w = tid >> 5;
    const int wm = (w & 3) * 32;      // warp m offset within tile
    const int wn = (w >> 2) * 32;     // warp n offset within tile

    float d[2][4][4];
    #pragma unroll
    for (int mt = 0; mt < 2; mt++)
        #pragma unroll
        for (int nt = 0; nt < 4; nt++)
            #pragma unroll
            for (int q = 0; q < 4; q++) d[mt][nt][q] = 0.f;

    // per-lane ldmatrix base addresses (bytes)
    const uint32_t sbase = smem_u32(sm);
    const int t = lane >> 3, r8 = lane & 7;
    // A tiles: order (m0,k0),(m8,k0),(m0,k8),(m8,k8)
    uint32_t aA[2];
    #pragma unroll
    for (int mt = 0; mt < 2; mt++) {
        int row = wm + mt * 16 + (t & 1) * 8 + r8;
        aA[mt] = sbase + (uint32_t)(row * PITCH + (t >> 1) * 8) * 2;
    }
    const uint32_t ALO = 128 * PITCH * 2;
    // B tiles: order (n0,k0),(n0,k8),(n8,k0),(n8,k8) per 16-n group g
    uint32_t aB[2];
    #pragma unroll
    for (int g = 0; g < 2; g++) {
        int row = wn + g * 16 + (t >> 1) * 8 + r8;
        aB[g] = sbase + 2 * 128 * PITCH * 2 + (uint32_t)(row * PITCH + (t & 1) * 8) * 2;
    }
    const uint32_t BLO = 64 * PITCH * 2;

    #pragma unroll
    for (int kk = 0; kk < 8; kk++) {
        const uint32_t ko = kk * 32;    // 16 bf16 = 32 bytes
        uint32_t ah[2][4], al[2][4], bh[2][4], bl[2][4];
        #pragma unroll
        for (int mt = 0; mt < 2; mt++) {
            LDSM4(ah[mt], aA[mt] + ko);
            LDSM4(al[mt], aA[mt] + ALO + ko);
        }
        #pragma unroll
        for (int g = 0; g < 2; g++) {
            LDSM4(bh[g], aB[g] + ko);
            LDSM4(bl[g], aB[g] + BLO + ko);
        }
        #pragma unroll
        for (int mt = 0; mt < 2; mt++)
            #pragma unroll
            for (int nt = 0; nt < 4; nt++) {
                int g = nt >> 1, o = (nt & 1) * 2;
                MMA_BF16(d[mt][nt], ah[mt], bh[g][o], bh[g][o + 1]);
                MMA_BF16(d[mt][nt], ah[mt], bl[g][o], bl[g][o + 1]);
                MMA_BF16(d[mt][nt], al[mt], bh[g][o], bh[g][o + 1]);
            }
    }

    // epilogue
    const int rr = lane >> 2, c2 = (lane & 3) * 2;
    #pragma unroll
    for (int mt = 0; mt < 2; mt++)
        #pragma unroll
        for (int nt = 0; nt < 4; nt++) {
            int col = n0 + wn + nt * 8 + c2;
            float b0 = bias[col], b1 = bias[col + 1];
            int row0 = m0 + wm + mt * 16 + rr;
            if (row0 < M) {
                float2 v = make_float2(d[mt][nt][0] + b0, d[mt][nt][1] + b1);
                *(float2*)(C + (size_t)row0 * N + col) = v;
            }
            int row1 = row0 + 8;
            if (row1 < M) {
                float2 v = make_float2(d[mt][nt][2] + b0, d[mt][nt][3] + b1);
                *(float2*)(C + (size_t)row1 * N + col) = v;
            }
        }
}

// ---------------- fused GRU gates ----------------
__global__ void gates_kernel(const float* __restrict__ h, float* __restrict__ out) {
    int idx = blockIdx.x * blockDim.x + threadIdx.x;
    if (idx >= NNODES * H) return;
    int n = idx >> 7;
    int j = idx & 127;
    size_t b = (size_t)n * 3 * H;
    float ir = g_gi[b + j],        hr = g_gh[b + j];
    float iz = g_gi[b + H + j],    hz = g_gh[b + H + j];
    float in_ = g_gi[b + 2*H + j], hn = g_gh[b + 2*H + j];
    float r = 1.f / (1.f + __expf(-(ir + hr)));
    float z = 1.f / (1.f + __expf(-(iz + hz)));
    float nn = tanhf(in_ + r * hn);
    out[idx] = (1.f - z) * nn + z * h[idx];
}

// ---------------- launch ----------------
extern "C" void kernel_launch(void* const* d_in, const int* in_sizes, int n_in,
                              void* d_out, int out_size) {
    const float* h     = (const float*)d_in[0];
    const int*   eidx  = (const int*)  d_in[1];
    const int*   etype = (const int*)  d_in[2];
    const float* W_msg = (const float*)d_in[4];
    const float* b_msg = (const float*)d_in[5];
    const float* emb   = (const float*)d_in[6];
    const float* W_ih  = (const float*)d_in[7];
    const float* W_hh  = (const float*)d_in[8];
    const float* b_ih  = (const float*)d_in[9];
    const float* b_hh  = (const float*)d_in[10];
    float* out = (float*)d_out;

    float *hW, *gi, *gh;
    __nv_bfloat16 *hhi, *hlo, *mhi, *mlo, *whi, *wlo;
    cudaGetSymbolAddress((void**)&hW,  g_hW);
    cudaGetSymbolAddress((void**)&gi,  g_gi);
    cudaGetSymbolAddress((void**)&gh,  g_gh);
    cudaGetSymbolAddress((void**)&hhi, g_hhi);
    cudaGetSymbolAddress((void**)&hlo, g_hlo);
    cudaGetSymbolAddress((void**)&mhi, g_mhi);
    cudaGetSymbolAddress((void**)&mlo, g_mlo);
    cudaGetSymbolAddress((void**)&whi, g_whi);
    cudaGetSymbolAddress((void**)&wlo, g_wlo);

    cudaFuncSetAttribute(mma_gemm, cudaFuncAttributeMaxDynamicSharedMemorySize,
                         MMA_SMEM);

    const int GB = (NNODES + 127) / 128;   // 391
    const int W_IH_OFF = 128 * H;
    const int W_HH_OFF = (128 + 384) * H;

    zero_deg_kernel<<<(NNODES + 255) / 256, 256>>>();
    count_kernel  <<<(NEDGES + 255) / 256, 256>>>(eidx);

    // conversions
    convert_kernel<<<(NNODES * H / 4 + 255) / 256, 256>>>(h, hhi, hlo, NNODES * H / 4);
    convert_kernel<<<(128 * H / 4 + 255) / 256, 256>>>(W_msg, whi, wlo, 128 * H / 4);
    convert_kernel<<<(384 * H / 4 + 255) / 256, 256>>>(W_ih, whi + W_IH_OFF, wlo + W_IH_OFF, 384 * H / 4);
    convert_kernel<<<(384 * H / 4 + 255) / 256, 256>>>(W_hh, whi + W_HH_OFF, wlo + W_HH_OFF, 384 * H / 4);

    // hW = h @ W_msg^T + b_msg
    mma_gemm<<<dim3(GB, 2), 256, MMA_SMEM>>>(hhi, hlo, whi, wlo, b_msg, hW,
                                             NNODES, 128);
    scan1_kernel<<<NSB, SBLK>>>();
    scan2_kernel<<<1, 128>>>();
    scan3_kernel<<<NSB, SBLK>>>();
    scatter_kernel<<<(NEDGES + 255) / 256, 256>>>(eidx);
    aggregate_kernel<<<(NNODES * 32 + 255) / 256, 256>>>(eidx, etype, emb);

    // gi = msg @ W_ih^T + b_ih ; gh = h @ W_hh^T + b_hh
    mma_gemm<<<dim3(GB, 6), 256, MMA_SMEM>>>(mhi, mlo, whi + W_IH_OFF, wlo + W_IH_OFF,
                                             b_ih, gi, NNODES, 384);
    mma_gemm<<<dim3(GB, 6), 256, MMA_SMEM>>>(hhi, hlo, whi + W_HH_OFF, wlo + W_HH_OFF,
                                             b_hh, gh, NNODES, 384);
    gates_kernel<<<(NNODES * H + 255) / 256, 256>>>(h, out);
}